// round 10
// baseline (speedup 1.0000x reference)
#include <cuda_runtime.h>

#define N_ATOMS 100000
#define N_PAIRS 3200000
#define ZMAX    96
#define NBLK    148
#define NTHR    512
#define TILE    2048
#define NTILES  ((N_PAIRS + TILE - 1) / TILE)   // 1563 (last tile = 1024 pairs)
#define STAGES  3

// smem layout (bytes)
#define Z8_OFF   0
#define ZPOW_OFF (N_ATOMS)                       // 100000 (16B aligned)
#define STG_OFF  (N_ATOMS + ZMAX * 4)            // 100384 (16B aligned)
#define STG_SZ   (TILE * 16)                     // 32768: d|ct|ii|jj, 8192B each
#define BAR_OFF  (STG_OFF + STAGES * STG_SZ)     // 198688 (8B aligned)
#define SMEM_BYTES (BAR_OFF + 64)

// Scratch (no allocation allowed)
__device__ __align__(16) unsigned char g_z8[N_ATOMS];  // Z in [1,95), 100KB
__device__ float  g_zpow[ZMAX];                        // z^|a_exponent| LUT
__device__ float4 g_params4[3];                        // [0]=c  [1]=e  [2]={inv_a,K,-,-}

// ---------------- PTX helpers (inline, self-contained) ----------------
__device__ __forceinline__ unsigned smem_u32(const void* p) {
    return (unsigned)__cvta_generic_to_shared(p);
}
__device__ __forceinline__ void mbar_init(unsigned a, unsigned cnt) {
    asm volatile("mbarrier.init.shared.b64 [%0], %1;" :: "r"(a), "r"(cnt) : "memory");
}
__device__ __forceinline__ void mbar_expect_tx(unsigned a, unsigned bytes) {
    asm volatile("mbarrier.arrive.expect_tx.shared.b64 _, [%0], %1;"
                 :: "r"(a), "r"(bytes) : "memory");
}
__device__ __forceinline__ void mbar_wait(unsigned a, unsigned parity) {
    asm volatile(
        "{\n\t.reg .pred P;\n"
        "W%=:\n\t"
        "mbarrier.try_wait.parity.shared.b64 P, [%0], %1;\n\t"
        "@P bra D%=;\n\t"
        "bra W%=;\n"
        "D%=:\n\t}"
        :: "r"(a), "r"(parity) : "memory");
}
__device__ __forceinline__ void bulk_g2s(unsigned dst, const void* src,
                                         unsigned bytes, unsigned bar) {
    asm volatile(
        "cp.async.bulk.shared::cluster.global.mbarrier::complete_tx::bytes "
        "[%0], [%1], %2, [%3];"
        :: "r"(dst), "l"(src), "r"(bytes), "r"(bar) : "memory");
}
// -----------------------------------------------------------------------

__global__ void __launch_bounds__(256) prep_kernel(
    const int* __restrict__ Z,
    const float* __restrict__ a_coef, const float* __restrict__ a_exp,
    const float* __restrict__ phi_c,  const float* __restrict__ phi_e,
    const float* __restrict__ ke,     const float* __restrict__ d2A,
    const float* __restrict__ e2m,
    float* __restrict__ out)
{
    int n = blockIdx.x * blockDim.x + threadIdx.x;
    if (n == 0) {
        float a0 = fabsf(phi_c[0]), a1 = fabsf(phi_c[1]),
              a2 = fabsf(phi_c[2]), a3 = fabsf(phi_c[3]);
        float inv_s = 1.0f / (a0 + a1 + a2 + a3);
        g_params4[0] = make_float4(a0 * inv_s, a1 * inv_s, a2 * inv_s, a3 * inv_s);
        g_params4[1] = make_float4(fabsf(phi_e[0]), fabsf(phi_e[1]),
                                   fabsf(phi_e[2]), fabsf(phi_e[3]));
        g_params4[2] = make_float4(1.0f / fabsf(a_coef[0]),
                                   ke[0] * e2m[0] / d2A[0], 0.0f, 0.0f);
    }
    if (n < ZMAX) {
        g_zpow[n] = __powf((float)n, fabsf(a_exp[0]));
    }
    if (n < N_ATOMS) {
        g_z8[n] = (unsigned char)Z[n];
        out[n] = 0.0f;                     // d_out poisoned -> zero it
    }
}

__global__ void __launch_bounds__(NTHR, 1) pair_kernel(
    const float* __restrict__ dist, const float* __restrict__ cut,
    const int*  __restrict__ idx_i, const int*  __restrict__ idx_j,
    float* __restrict__ out)
{
    extern __shared__ unsigned char smem[];
    unsigned char* s_z8   = smem + Z8_OFF;
    float*         s_zpow = (float*)(smem + ZPOW_OFF);
    const unsigned smem_base = smem_u32(smem);
    const unsigned bar_base  = smem_base + BAR_OFF;

    int tid = threadIdx.x;
    int bid = blockIdx.x;

    // mbarriers (one "full" barrier per stage)
    if (tid == 0) {
        #pragma unroll
        for (int s = 0; s < STAGES; s++) mbar_init(bar_base + 8 * s, 1);
    }
    // Stage the 100KB Z table + LUT into smem
    {
        const int4* src = (const int4*)g_z8;
        int4*       dst = (int4*)s_z8;
        #pragma unroll 4
        for (int i = tid; i < N_ATOMS / 16; i += NTHR) dst[i] = src[i];
        if (tid < ZMAX) s_zpow[tid] = g_zpow[tid];
    }
    __syncthreads();

    const int nt_cta = (NTILES - bid + NBLK - 1) / NBLK;   // tiles for this CTA

    // Prologue: issue up to STAGES tiles
    if (tid == 0) {
        #pragma unroll
        for (int s = 0; s < STAGES; s++) {
            if (s < nt_cta) {
                int tile = bid + s * NBLK;
                unsigned bytes = (unsigned)(min(TILE, N_PAIRS - tile * TILE) * 4);
                unsigned bar = bar_base + 8 * s;
                unsigned dst = smem_base + STG_OFF + s * STG_SZ;
                long off = (long)tile * TILE;
                mbar_expect_tx(bar, 4 * bytes);
                bulk_g2s(dst,             dist  + off, bytes, bar);
                bulk_g2s(dst + 8192,      cut   + off, bytes, bar);
                bulk_g2s(dst + 16384,     idx_i + off, bytes, bar);
                bulk_g2s(dst + 24576,     idx_j + off, bytes, bar);
            }
        }
    }

    float4 C  = g_params4[0];
    float4 E  = g_params4[1];
    float4 P2 = g_params4[2];
    float inv_a = P2.x, K = P2.y;

    const unsigned m = 0xffffffffu;
    int lane = tid & 31;
    unsigned mask_le = 0xffffffffu >> (31 - lane);

    for (int k = 0; k < nt_cta; k++) {
        int stage = k % STAGES;
        int tile  = bid + k * NBLK;
        int tsize = min(TILE, N_PAIRS - tile * TILE);
        unsigned char* stg = smem + STG_OFF + stage * STG_SZ;
        const float* s_d  = (const float*)(stg);
        const float* s_ct = (const float*)(stg + 8192);
        const int*   s_ii = (const int*)  (stg + 16384);
        const int*   s_jj = (const int*)  (stg + 24576);

        mbar_wait(bar_base + 8 * stage, (k / STAGES) & 1);

        int lt = tid * 4;                     // 4 contiguous pairs per thread
        if (lt < tsize) {                     // whole warps valid/invalid (1024|2048 % 128 == 0)
            float4 d  = *(const float4*)(s_d  + lt);
            float4 ct = *(const float4*)(s_ct + lt);
            int4   si = *(const int4*)  (s_ii + lt);
            int4   sj = *(const int4*)  (s_jj + lt);

            int zi0 = s_z8[si.x], zi1 = s_z8[si.y], zi2 = s_z8[si.z], zi3 = s_z8[si.w];
            int zj0 = s_z8[sj.x], zj1 = s_z8[sj.y], zj2 = s_z8[sj.z], zj3 = s_z8[sj.w];

            float a0 = d.x * (s_zpow[zi0] + s_zpow[zj0]) * inv_a;
            float a1 = d.y * (s_zpow[zi1] + s_zpow[zj1]) * inv_a;
            float a2 = d.z * (s_zpow[zi2] + s_zpow[zj2]) * inv_a;
            float a3 = d.w * (s_zpow[zi3] + s_zpow[zj3]) * inv_a;

            float p0 = C.x * __expf(-E.x * a0) + C.y * __expf(-E.y * a0)
                     + C.z * __expf(-E.z * a0) + C.w * __expf(-E.w * a0);
            float p1 = C.x * __expf(-E.x * a1) + C.y * __expf(-E.y * a1)
                     + C.z * __expf(-E.z * a1) + C.w * __expf(-E.w * a1);
            float p2 = C.x * __expf(-E.x * a2) + C.y * __expf(-E.y * a2)
                     + C.z * __expf(-E.z * a2) + C.w * __expf(-E.w * a2);
            float p3 = C.x * __expf(-E.x * a3) + C.y * __expf(-E.y * a3)
                     + C.z * __expf(-E.z * a3) + C.w * __expf(-E.w * a3);

            float v0 = K * (float)(zi0 * zj0) * p0 * ct.x * __fdividef(1.0f, d.x);
            float v1 = K * (float)(zi1 * zj1) * p1 * ct.y * __fdividef(1.0f, d.y);
            float v2 = K * (float)(zi2 * zj2) * p2 * ct.z * __fdividef(1.0f, d.z);
            float v3 = K * (float)(zi3 * zj3) * p3 * ct.w * __fdividef(1.0f, d.w);

            // In-thread serial segmented combine (idx_i sorted)
            int   seg = si.x;
            float acc = v0;
            #define ZSTEP(S, V) \
                if ((S) == seg) acc += (V); \
                else { atomicAdd(&out[seg], acc); seg = (S); acc = (V); }
            ZSTEP(si.y, v1) ZSTEP(si.z, v2) ZSTEP(si.w, v3)
            #undef ZSTEP

            // Warp segmented inclusive scan over (seg, acc); tails do atomics
            int segp = __shfl_up_sync(m, seg, 1);
            bool head = (lane == 0) || (segp != seg);
            unsigned hb = __ballot_sync(m, head);
            int head_lane = 31 - __clz(hb & mask_le);
            #pragma unroll
            for (int off = 1; off < 32; off <<= 1) {
                float vv = __shfl_up_sync(m, acc, off);
                if (lane - off >= head_lane) acc += vv;
            }
            unsigned tails = (hb >> 1) | 0x80000000u;
            if ((tails >> lane) & 1) {
                atomicAdd(&out[seg], acc);
            }
        }
        __syncthreads();   // all consumed this stage before refill

        if (tid == 0 && k + STAGES < nt_cta) {
            int ntile = bid + (k + STAGES) * NBLK;
            unsigned bytes = (unsigned)(min(TILE, N_PAIRS - ntile * TILE) * 4);
            unsigned bar = bar_base + 8 * stage;
            unsigned dst = smem_base + STG_OFF + stage * STG_SZ;
            long off = (long)ntile * TILE;
            mbar_expect_tx(bar, 4 * bytes);
            bulk_g2s(dst,         dist  + off, bytes, bar);
            bulk_g2s(dst + 8192,  cut   + off, bytes, bar);
            bulk_g2s(dst + 16384, idx_i + off, bytes, bar);
            bulk_g2s(dst + 24576, idx_j + off, bytes, bar);
        }
    }
}

extern "C" void kernel_launch(void* const* d_in, const int* in_sizes, int n_in,
                              void* d_out, int out_size)
{
    const int*   Z    = (const int*)  d_in[0];
    const float* dist = (const float*)d_in[1];
    const float* cutv = (const float*)d_in[2];
    const int*   ii   = (const int*)  d_in[3];
    const int*   jj   = (const int*)  d_in[4];
    const float* ac   = (const float*)d_in[5];
    const float* ae   = (const float*)d_in[6];
    const float* pc   = (const float*)d_in[7];
    const float* pe   = (const float*)d_in[8];
    const float* ke   = (const float*)d_in[9];
    const float* d2A  = (const float*)d_in[10];
    const float* e2m  = (const float*)d_in[11];
    float* out = (float*)d_out;

    cudaFuncSetAttribute(pair_kernel,
                         cudaFuncAttributeMaxDynamicSharedMemorySize, SMEM_BYTES);

    prep_kernel<<<(N_ATOMS + 255) / 256, 256>>>(Z, ac, ae, pc, pe, ke, d2A, e2m, out);
    pair_kernel<<<NBLK, NTHR, SMEM_BYTES>>>(dist, cutv, ii, jj, out);
}

// round 11
// speedup vs baseline: 1.0480x; 1.0480x over previous
#include <cuda_runtime.h>

#define N_ATOMS 100000
#define N_PAIRS 3200000
#define NT8     (N_PAIRS / 8)   // 400000 thread-work-items, exact
#define ZMAX    96
#define NBLK    148
#define NTHR    1024
#define NLUT    4096
#define U0      0.9f
#define U1      29.0f
#define LUT_H   ((U1 - U0) / NLUT)
#define LUT_SCALE (1.0f / LUT_H)
#define LUT_BIAS  (-U0 / LUT_H)

// smem: z8 table | zl (float2[96]) | G lut (float2[4096])
#define ZL_OFF   (N_ATOMS)               // 100000, 8B aligned
#define LUT_OFF  (N_ATOMS + ZMAX * 8)    // 100768, 8B aligned
#define SMEM_BYTES (LUT_OFF + NLUT * 8)  // 133536

// Scratch (no allocation allowed)
__device__ __align__(16) unsigned char g_z8[N_ATOMS];  // Z in [1,95), 100KB
__device__ __align__(16) float2 g_zl[ZMAX];            // {z^|a_exp|, (float)z}
__device__ __align__(16) float2 g_lut[NLUT];           // {G_i, G_{i+1}-G_i}

// 256-bit streaming loads with L2 evict_last (sm_103a: hint requires v8.b32).
__device__ __forceinline__ void ldg_el_8f(const float* p, float4& a, float4& b) {
    asm("ld.global.nc.L2::evict_last.v8.b32 {%0,%1,%2,%3,%4,%5,%6,%7}, [%8];"
        : "=f"(a.x), "=f"(a.y), "=f"(a.z), "=f"(a.w),
          "=f"(b.x), "=f"(b.y), "=f"(b.z), "=f"(b.w)
        : "l"(p));
}
__device__ __forceinline__ void ldg_el_8i(const int* p, int4& a, int4& b) {
    asm("ld.global.nc.L2::evict_last.v8.b32 {%0,%1,%2,%3,%4,%5,%6,%7}, [%8];"
        : "=r"(a.x), "=r"(a.y), "=r"(a.z), "=r"(a.w),
          "=r"(b.x), "=r"(b.y), "=r"(b.z), "=r"(b.w)
        : "l"(p));
}

__device__ __forceinline__ float eval_G(float u, float inv_a, float K,
                                        float4 C, float4 E)
{
    // G(u) = K * phi(u*inv_a) / u   (double-free, fp32 host-equivalent)
    float arg = u * inv_a;
    float phi = C.x * expf(-E.x * arg)
              + C.y * expf(-E.y * arg)
              + C.z * expf(-E.z * arg)
              + C.w * expf(-E.w * arg);
    return K * phi / u;
}

__global__ void __launch_bounds__(256) prep_kernel(
    const int* __restrict__ Z,
    const float* __restrict__ a_coef, const float* __restrict__ a_exp,
    const float* __restrict__ phi_c,  const float* __restrict__ phi_e,
    const float* __restrict__ ke,     const float* __restrict__ d2A,
    const float* __restrict__ e2m,
    float* __restrict__ out)
{
    int n = blockIdx.x * blockDim.x + threadIdx.x;

    if (n < NLUT || n < ZMAX) {
        // each thread derives params redundantly (cheap, no sync needed)
        float a0 = fabsf(phi_c[0]), a1 = fabsf(phi_c[1]),
              a2 = fabsf(phi_c[2]), a3 = fabsf(phi_c[3]);
        float inv_s = 1.0f / (a0 + a1 + a2 + a3);
        float4 C = make_float4(a0 * inv_s, a1 * inv_s, a2 * inv_s, a3 * inv_s);
        float4 E = make_float4(fabsf(phi_e[0]), fabsf(phi_e[1]),
                               fabsf(phi_e[2]), fabsf(phi_e[3]));
        float inv_a = 1.0f / fabsf(a_coef[0]);
        float K     = ke[0] * e2m[0] / d2A[0];
        if (n < NLUT) {
            float x0 = U0 + n * LUT_H;
            float g0 = eval_G(x0,         inv_a, K, C, E);
            float g1 = eval_G(x0 + LUT_H, inv_a, K, C, E);
            g_lut[n] = make_float2(g0, g1 - g0);
        }
        if (n < ZMAX) {
            float zf = (float)n;
            g_zl[n] = make_float2(__powf(zf, fabsf(a_exp[0])), zf);
        }
    }
    if (n < N_ATOMS) {
        g_z8[n] = (unsigned char)Z[n];
        out[n] = 0.0f;                     // d_out poisoned -> zero it
    }
}

__device__ __forceinline__ float pair_val(
    float d, float ct, int zi, int zj,
    const float2* __restrict__ s_zl, const float2* __restrict__ s_lut)
{
    float2 li = s_zl[zi], lj = s_zl[zj];
    float s = li.x + lj.x;                 // za_i + za_j
    float u = d * s;
    float t = fmaf(u, LUT_SCALE, LUT_BIAS);
    t = fminf(fmaxf(t, 0.0f), (float)(NLUT - 1) - 0.001f);
    int ix = (int)t;
    float fr = t - (float)ix;
    float2 e = s_lut[ix];
    float G = fmaf(fr, e.y, e.x);          // K*phi(arg)/u
    return li.y * lj.y * ct * s * G;       // Zi*Zj*ct*s*G  (1/d = s/u folded)
}

__global__ void __launch_bounds__(NTHR, 1) pair_kernel(
    const float* __restrict__ dist, const float* __restrict__ cut,
    const int*  __restrict__ idx_i, const int*  __restrict__ idx_j,
    float* __restrict__ out)
{
    extern __shared__ unsigned char smem[];
    unsigned char* s_z8  = smem;
    float2*        s_zl  = (float2*)(smem + ZL_OFF);
    float2*        s_lut = (float2*)(smem + LUT_OFF);

    // Stage tables into smem (L2-resident sources)
    {
        const int4* src = (const int4*)g_z8;
        int4*       dst = (int4*)s_z8;
        #pragma unroll 4
        for (int i = threadIdx.x; i < N_ATOMS / 16; i += NTHR) dst[i] = src[i];
        const int4* lsrc = (const int4*)g_lut;
        int4*       ldst = (int4*)s_lut;
        #pragma unroll 2
        for (int i = threadIdx.x; i < NLUT / 2; i += NTHR) ldst[i] = lsrc[i];
        if (threadIdx.x < ZMAX) s_zl[threadIdx.x] = g_zl[threadIdx.x];
    }
    __syncthreads();

    for (int t = blockIdx.x * NTHR + threadIdx.x; t < NT8; t += NBLK * NTHR) {
        // Front-batch 4 x 256-bit stream loads (evict_last, MLP_p1=4)
        int4 siA, siB, sjA, sjB;
        float4 dA, dB, ctA, ctB;
        ldg_el_8i(idx_i + 8 * t, siA, siB);
        ldg_el_8i(idx_j + 8 * t, sjA, sjB);
        ldg_el_8f(dist  + 8 * t, dA,  dB);
        ldg_el_8f(cut   + 8 * t, ctA, ctB);

        int ziA0 = s_z8[siA.x], ziA1 = s_z8[siA.y], ziA2 = s_z8[siA.z], ziA3 = s_z8[siA.w];
        int zjA0 = s_z8[sjA.x], zjA1 = s_z8[sjA.y], zjA2 = s_z8[sjA.z], zjA3 = s_z8[sjA.w];
        int ziB0 = s_z8[siB.x], ziB1 = s_z8[siB.y], ziB2 = s_z8[siB.z], ziB3 = s_z8[siB.w];
        int zjB0 = s_z8[sjB.x], zjB1 = s_z8[sjB.y], zjB2 = s_z8[sjB.z], zjB3 = s_z8[sjB.w];

        float v0 = pair_val(dA.x, ctA.x, ziA0, zjA0, s_zl, s_lut);
        float v1 = pair_val(dA.y, ctA.y, ziA1, zjA1, s_zl, s_lut);
        float v2 = pair_val(dA.z, ctA.z, ziA2, zjA2, s_zl, s_lut);
        float v3 = pair_val(dA.w, ctA.w, ziA3, zjA3, s_zl, s_lut);
        float v4 = pair_val(dB.x, ctB.x, ziB0, zjB0, s_zl, s_lut);
        float v5 = pair_val(dB.y, ctB.y, ziB1, zjB1, s_zl, s_lut);
        float v6 = pair_val(dB.z, ctB.z, ziB2, zjB2, s_zl, s_lut);
        float v7 = pair_val(dB.w, ctB.w, ziB3, zjB3, s_zl, s_lut);

        // Thread-local segmented accumulation; fire-and-forget atomics at
        // boundaries (idx_i sorted, ~32 pairs/segment -> ~1.25 atomics/iter).
        int   seg = siA.x;
        float acc = v0;
        #define ZSTEP(S, V) \
            if ((S) == seg) acc += (V); \
            else { atomicAdd(&out[seg], acc); seg = (S); acc = (V); }
        ZSTEP(siA.y, v1) ZSTEP(siA.z, v2) ZSTEP(siA.w, v3)
        ZSTEP(siB.x, v4) ZSTEP(siB.y, v5) ZSTEP(siB.z, v6) ZSTEP(siB.w, v7)
        #undef ZSTEP
        atomicAdd(&out[seg], acc);
    }
}

extern "C" void kernel_launch(void* const* d_in, const int* in_sizes, int n_in,
                              void* d_out, int out_size)
{
    const int*   Z    = (const int*)  d_in[0];
    const float* dist = (const float*)d_in[1];
    const float* cutv = (const float*)d_in[2];
    const int*   ii   = (const int*)  d_in[3];
    const int*   jj   = (const int*)  d_in[4];
    const float* ac   = (const float*)d_in[5];
    const float* ae   = (const float*)d_in[6];
    const float* pc   = (const float*)d_in[7];
    const float* pe   = (const float*)d_in[8];
    const float* ke   = (const float*)d_in[9];
    const float* d2A  = (const float*)d_in[10];
    const float* e2m  = (const float*)d_in[11];
    float* out = (float*)d_out;

    cudaFuncSetAttribute(pair_kernel,
                         cudaFuncAttributeMaxDynamicSharedMemorySize, SMEM_BYTES);

    prep_kernel<<<(N_ATOMS + 255) / 256, 256>>>(Z, ac, ae, pc, pe, ke, d2A, e2m, out);
    pair_kernel<<<NBLK, NTHR, SMEM_BYTES>>>(dist, cutv, ii, jj, out);
}

// round 12
// speedup vs baseline: 1.0935x; 1.0434x over previous
#include <cuda_runtime.h>

#define N_ATOMS 100000
#define N_PAIRS 3200000
#define NT8     (N_PAIRS / 8)   // 400000 thread-work-items, exact
#define ZMAX    96
#define NBLK    296              // two CTAs per SM
#define NTHR    512
#define SMEM_BYTES (N_ATOMS + ZMAX * 4)   // 100384 bytes dynamic smem

// Scratch (no allocation allowed)
__device__ __align__(16) unsigned char g_z8[N_ATOMS];  // Z in [1,95), 100KB
__device__ float  g_zpow[ZMAX];                        // z^|a_exponent| LUT
__device__ float4 g_params4[3];                        // [0]=c  [1]=e  [2]={inv_a,K,-,-}

// 256-bit streaming loads with L2 evict_last (sm_103a: hint requires v8.b32).
__device__ __forceinline__ void ldg_el_8f(const float* p, float4& a, float4& b) {
    asm("ld.global.nc.L2::evict_last.v8.b32 {%0,%1,%2,%3,%4,%5,%6,%7}, [%8];"
        : "=f"(a.x), "=f"(a.y), "=f"(a.z), "=f"(a.w),
          "=f"(b.x), "=f"(b.y), "=f"(b.z), "=f"(b.w)
        : "l"(p));
}
__device__ __forceinline__ void ldg_el_8i(const int* p, int4& a, int4& b) {
    asm("ld.global.nc.L2::evict_last.v8.b32 {%0,%1,%2,%3,%4,%5,%6,%7}, [%8];"
        : "=r"(a.x), "=r"(a.y), "=r"(a.z), "=r"(a.w),
          "=r"(b.x), "=r"(b.y), "=r"(b.z), "=r"(b.w)
        : "l"(p));
}

__global__ void __launch_bounds__(256) prep_kernel(
    const int* __restrict__ Z,
    const float* __restrict__ a_coef, const float* __restrict__ a_exp,
    const float* __restrict__ phi_c,  const float* __restrict__ phi_e,
    const float* __restrict__ ke,     const float* __restrict__ d2A,
    const float* __restrict__ e2m,
    float* __restrict__ out)
{
    int n = blockIdx.x * blockDim.x + threadIdx.x;
    if (n == 0) {
        float a0 = fabsf(phi_c[0]), a1 = fabsf(phi_c[1]),
              a2 = fabsf(phi_c[2]), a3 = fabsf(phi_c[3]);
        float inv_s = 1.0f / (a0 + a1 + a2 + a3);
        g_params4[0] = make_float4(a0 * inv_s, a1 * inv_s, a2 * inv_s, a3 * inv_s);
        g_params4[1] = make_float4(fabsf(phi_e[0]), fabsf(phi_e[1]),
                                   fabsf(phi_e[2]), fabsf(phi_e[3]));
        g_params4[2] = make_float4(1.0f / fabsf(a_coef[0]),
                                   ke[0] * e2m[0] / d2A[0], 0.0f, 0.0f);
    }
    if (n < ZMAX) {
        g_zpow[n] = __powf((float)n, fabsf(a_exp[0]));
    }
    if (n < N_ATOMS) {
        g_z8[n] = (unsigned char)Z[n];
        out[n] = 0.0f;                     // d_out poisoned -> zero it
    }
}

__device__ __forceinline__ float pair_val(
    float d, float ct, int zi, int zj, const float* __restrict__ s_zpow,
    float4 C, float4 E, float inv_a, float K)
{
    float arg = d * (s_zpow[zi] + s_zpow[zj]) * inv_a;
    float phi = C.x * __expf(-E.x * arg)
              + C.y * __expf(-E.y * arg)
              + C.z * __expf(-E.z * arg)
              + C.w * __expf(-E.w * arg);
    return K * (float)(zi * zj) * phi * ct * __fdividef(1.0f, d);
}

__global__ void __launch_bounds__(NTHR, 2) pair_kernel(
    const float* __restrict__ dist, const float* __restrict__ cut,
    const int*  __restrict__ idx_i, const int*  __restrict__ idx_j,
    float* __restrict__ out)
{
    extern __shared__ unsigned char smem[];
    unsigned char* s_z8   = smem;
    float*         s_zpow = (float*)(smem + N_ATOMS);   // N_ATOMS % 16 == 0

    // Stage 100KB Z table into smem (L2-resident source)
    {
        const int4* src = (const int4*)g_z8;
        int4*       dst = (int4*)s_z8;
        #pragma unroll 4
        for (int i = threadIdx.x; i < N_ATOMS / 16; i += NTHR) dst[i] = src[i];
        if (threadIdx.x < ZMAX) s_zpow[threadIdx.x] = g_zpow[threadIdx.x];
    }
    __syncthreads();

    float4 C  = g_params4[0];
    float4 E  = g_params4[1];
    float4 P2 = g_params4[2];
    float inv_a = P2.x, K = P2.y;

    for (int t = blockIdx.x * NTHR + threadIdx.x; t < NT8; t += NBLK * NTHR) {
        // Front-batch 4 x 256-bit stream loads (evict_last, MLP_p1=4)
        int4 siA, siB, sjA, sjB;
        float4 dA, dB, ctA, ctB;
        ldg_el_8i(idx_i + 8 * t, siA, siB);
        ldg_el_8i(idx_j + 8 * t, sjA, sjB);
        ldg_el_8f(dist  + 8 * t, dA,  dB);
        ldg_el_8f(cut   + 8 * t, ctA, ctB);

        // smem gathers (zi nearly uniform -> broadcast; zj random -> low conflict)
        int ziA0 = s_z8[siA.x], ziA1 = s_z8[siA.y], ziA2 = s_z8[siA.z], ziA3 = s_z8[siA.w];
        int zjA0 = s_z8[sjA.x], zjA1 = s_z8[sjA.y], zjA2 = s_z8[sjA.z], zjA3 = s_z8[sjA.w];
        int ziB0 = s_z8[siB.x], ziB1 = s_z8[siB.y], ziB2 = s_z8[siB.z], ziB3 = s_z8[siB.w];
        int zjB0 = s_z8[sjB.x], zjB1 = s_z8[sjB.y], zjB2 = s_z8[sjB.z], zjB3 = s_z8[sjB.w];

        float v0 = pair_val(dA.x, ctA.x, ziA0, zjA0, s_zpow, C, E, inv_a, K);
        float v1 = pair_val(dA.y, ctA.y, ziA1, zjA1, s_zpow, C, E, inv_a, K);
        float v2 = pair_val(dA.z, ctA.z, ziA2, zjA2, s_zpow, C, E, inv_a, K);
        float v3 = pair_val(dA.w, ctA.w, ziA3, zjA3, s_zpow, C, E, inv_a, K);
        float v4 = pair_val(dB.x, ctB.x, ziB0, zjB0, s_zpow, C, E, inv_a, K);
        float v5 = pair_val(dB.y, ctB.y, ziB1, zjB1, s_zpow, C, E, inv_a, K);
        float v6 = pair_val(dB.z, ctB.z, ziB2, zjB2, s_zpow, C, E, inv_a, K);
        float v7 = pair_val(dB.w, ctB.w, ziB3, zjB3, s_zpow, C, E, inv_a, K);

        // Thread-local segmented accumulation; fire-and-forget atomics at
        // boundaries (idx_i sorted, ~32 pairs/segment -> ~1.25 atomics/iter).
        int   seg = siA.x;
        float acc = v0;
        #define ZSTEP(S, V) \
            if ((S) == seg) acc += (V); \
            else { atomicAdd(&out[seg], acc); seg = (S); acc = (V); }
        ZSTEP(siA.y, v1) ZSTEP(siA.z, v2) ZSTEP(siA.w, v3)
        ZSTEP(siB.x, v4) ZSTEP(siB.y, v5) ZSTEP(siB.z, v6) ZSTEP(siB.w, v7)
        #undef ZSTEP
        atomicAdd(&out[seg], acc);
    }
}

extern "C" void kernel_launch(void* const* d_in, const int* in_sizes, int n_in,
                              void* d_out, int out_size)
{
    const int*   Z    = (const int*)  d_in[0];
    const float* dist = (const float*)d_in[1];
    const float* cutv = (const float*)d_in[2];
    const int*   ii   = (const int*)  d_in[3];
    const int*   jj   = (const int*)  d_in[4];
    const float* ac   = (const float*)d_in[5];
    const float* ae   = (const float*)d_in[6];
    const float* pc   = (const float*)d_in[7];
    const float* pe   = (const float*)d_in[8];
    const float* ke   = (const float*)d_in[9];
    const float* d2A  = (const float*)d_in[10];
    const float* e2m  = (const float*)d_in[11];
    float* out = (float*)d_out;

    cudaFuncSetAttribute(pair_kernel,
                         cudaFuncAttributeMaxDynamicSharedMemorySize, SMEM_BYTES);

    prep_kernel<<<(N_ATOMS + 255) / 256, 256>>>(Z, ac, ae, pc, pe, ke, d2A, e2m, out);
    pair_kernel<<<NBLK, NTHR, SMEM_BYTES>>>(dist, cutv, ii, jj, out);
}

// round 13
// speedup vs baseline: 1.1293x; 1.0328x over previous
#include <cuda_runtime.h>

#define N_ATOMS 100000
#define N_PAIRS 3200000
#define NT4     (N_PAIRS / 4)    // 800000 thread-work-items
#define ZMAX    96
#define NBLK    148
#define NTHR    1024
#define STRIDE  (NBLK * NTHR)    // 151552

// smem layout (bytes)
#define ZPOW_OFF N_ATOMS                     // 100000
#define RING_OFF (N_ATOMS + ZMAX * 4)        // 100384, 16B aligned
#define STAGE_F4 (3 * NTHR)                  // float4 slots per stage (d|ct|jj)
#define SMEM_BYTES (RING_OFF + 2 * STAGE_F4 * 16)   // 100384 + 98304 = 198688

// Scratch (no allocation allowed)
__device__ __align__(16) unsigned char g_z8[N_ATOMS];  // Z in [1,95), 100KB
__device__ float  g_zpow[ZMAX];                        // z^|a_exponent| LUT
__device__ float4 g_params4[3];                        // [0]=c  [1]=e  [2]={inv_a,K,-,-}

__device__ __forceinline__ void cp_async16(unsigned dst_smem, const void* src) {
    asm volatile("cp.async.cg.shared.global [%0], [%1], 16;"
                 :: "r"(dst_smem), "l"(src) : "memory");
}
__device__ __forceinline__ void cp_commit() {
    asm volatile("cp.async.commit_group;" ::: "memory");
}
__device__ __forceinline__ void cp_wait1() {
    asm volatile("cp.async.wait_group 1;" ::: "memory");
}

__global__ void __launch_bounds__(256) prep_kernel(
    const int* __restrict__ Z,
    const float* __restrict__ a_coef, const float* __restrict__ a_exp,
    const float* __restrict__ phi_c,  const float* __restrict__ phi_e,
    const float* __restrict__ ke,     const float* __restrict__ d2A,
    const float* __restrict__ e2m,
    float* __restrict__ out)
{
    int n = blockIdx.x * blockDim.x + threadIdx.x;
    if (n == 0) {
        float a0 = fabsf(phi_c[0]), a1 = fabsf(phi_c[1]),
              a2 = fabsf(phi_c[2]), a3 = fabsf(phi_c[3]);
        float inv_s = 1.0f / (a0 + a1 + a2 + a3);
        g_params4[0] = make_float4(a0 * inv_s, a1 * inv_s, a2 * inv_s, a3 * inv_s);
        g_params4[1] = make_float4(fabsf(phi_e[0]), fabsf(phi_e[1]),
                                   fabsf(phi_e[2]), fabsf(phi_e[3]));
        g_params4[2] = make_float4(1.0f / fabsf(a_coef[0]),
                                   ke[0] * e2m[0] / d2A[0], 0.0f, 0.0f);
    }
    if (n < ZMAX) {
        g_zpow[n] = __powf((float)n, fabsf(a_exp[0]));
    }
    if (n < N_ATOMS) {
        g_z8[n] = (unsigned char)Z[n];
        out[n] = 0.0f;                     // d_out poisoned -> zero it
    }
}

__global__ void __launch_bounds__(NTHR, 1) pair_kernel(
    const float* __restrict__ dist, const float* __restrict__ cut,
    const int*  __restrict__ idx_i, const int*  __restrict__ idx_j,
    float* __restrict__ out)
{
    extern __shared__ unsigned char smem[];
    unsigned char* s_z8   = smem;
    float*         s_zpow = (float*)(smem + ZPOW_OFF);
    float4*        ring   = (float4*)(smem + RING_OFF);

    int tid = threadIdx.x;

    // Stage 100KB Z table + LUT into smem (L2-resident source)
    {
        const int4* src = (const int4*)g_z8;
        int4*       dst = (int4*)s_z8;
        #pragma unroll 4
        for (int i = tid; i < N_ATOMS / 16; i += NTHR) dst[i] = src[i];
        if (tid < ZMAX) s_zpow[tid] = g_zpow[tid];
    }
    __syncthreads();

    float4 C  = g_params4[0];
    float4 E  = g_params4[1];
    float4 P2 = g_params4[2];
    float inv_a = P2.x, K = P2.y;

    // Per-thread private ring slots (no cross-thread sharing -> no barriers)
    const unsigned ring_base = (unsigned)__cvta_generic_to_shared(ring);
    const unsigned slot_d  = ring_base + (0 * NTHR + tid) * 16;
    const unsigned slot_ct = ring_base + (1 * NTHR + tid) * 16;
    const unsigned slot_jj = ring_base + (2 * NTHR + tid) * 16;
    const unsigned stage_bytes = STAGE_F4 * 16;

    int t = blockIdx.x * NTHR + tid;       // always < NT4 initially

    // Prologue: stage 0 in flight
    cp_async16(slot_d,  dist  + 4 * t);
    cp_async16(slot_ct, cut   + 4 * t);
    cp_async16(slot_jj, idx_j + 4 * t);
    int4 si_cur = __ldg((const int4*)idx_i + t);
    cp_commit();

    int k = 0;
    bool valid = true;
    while (valid) {
        int tn = t + STRIDE;
        bool vn = tn < NT4;
        // Issue next stage while current compute runs (keeps DRAM busy)
        unsigned off_n = ((k + 1) & 1) * stage_bytes;
        int4 si_next;
        if (vn) {
            cp_async16(slot_d  + off_n, dist  + 4 * tn);
            cp_async16(slot_ct + off_n, cut   + 4 * tn);
            cp_async16(slot_jj + off_n, idx_j + 4 * tn);
            si_next = __ldg((const int4*)idx_i + tn);
        }
        cp_commit();
        cp_wait1();                         // current stage's data is ready

        int base = ((k & 1) ? STAGE_F4 : 0) + tid;
        float4 d  = ring[base];
        float4 ct = ring[base + NTHR];
        int4   sj = *(const int4*)&ring[base + 2 * NTHR];
        int4   si = si_cur;

        int zi0 = s_z8[si.x], zi1 = s_z8[si.y], zi2 = s_z8[si.z], zi3 = s_z8[si.w];
        int zj0 = s_z8[sj.x], zj1 = s_z8[sj.y], zj2 = s_z8[sj.z], zj3 = s_z8[sj.w];

        float a0 = d.x * (s_zpow[zi0] + s_zpow[zj0]) * inv_a;
        float a1 = d.y * (s_zpow[zi1] + s_zpow[zj1]) * inv_a;
        float a2 = d.z * (s_zpow[zi2] + s_zpow[zj2]) * inv_a;
        float a3 = d.w * (s_zpow[zi3] + s_zpow[zj3]) * inv_a;

        float p0 = C.x * __expf(-E.x * a0) + C.y * __expf(-E.y * a0)
                 + C.z * __expf(-E.z * a0) + C.w * __expf(-E.w * a0);
        float p1 = C.x * __expf(-E.x * a1) + C.y * __expf(-E.y * a1)
                 + C.z * __expf(-E.z * a1) + C.w * __expf(-E.w * a1);
        float p2 = C.x * __expf(-E.x * a2) + C.y * __expf(-E.y * a2)
                 + C.z * __expf(-E.z * a2) + C.w * __expf(-E.w * a2);
        float p3 = C.x * __expf(-E.x * a3) + C.y * __expf(-E.y * a3)
                 + C.z * __expf(-E.z * a3) + C.w * __expf(-E.w * a3);

        float v0 = K * (float)(zi0 * zj0) * p0 * ct.x * __fdividef(1.0f, d.x);
        float v1 = K * (float)(zi1 * zj1) * p1 * ct.y * __fdividef(1.0f, d.y);
        float v2 = K * (float)(zi2 * zj2) * p2 * ct.z * __fdividef(1.0f, d.z);
        float v3 = K * (float)(zi3 * zj3) * p3 * ct.w * __fdividef(1.0f, d.w);

        // Thread-local segmented accumulation; fire-and-forget atomics at
        // boundaries (idx_i sorted, ~32 pairs/segment).
        int   seg = si.x;
        float acc = v0;
        #define ZSTEP(S, V) \
            if ((S) == seg) acc += (V); \
            else { atomicAdd(&out[seg], acc); seg = (S); acc = (V); }
        ZSTEP(si.y, v1) ZSTEP(si.z, v2) ZSTEP(si.w, v3)
        #undef ZSTEP
        atomicAdd(&out[seg], acc);

        si_cur = si_next;
        t = tn;
        valid = vn;
        k++;
    }
}

extern "C" void kernel_launch(void* const* d_in, const int* in_sizes, int n_in,
                              void* d_out, int out_size)
{
    const int*   Z    = (const int*)  d_in[0];
    const float* dist = (const float*)d_in[1];
    const float* cutv = (const float*)d_in[2];
    const int*   ii   = (const int*)  d_in[3];
    const int*   jj   = (const int*)  d_in[4];
    const float* ac   = (const float*)d_in[5];
    const float* ae   = (const float*)d_in[6];
    const float* pc   = (const float*)d_in[7];
    const float* pe   = (const float*)d_in[8];
    const float* ke   = (const float*)d_in[9];
    const float* d2A  = (const float*)d_in[10];
    const float* e2m  = (const float*)d_in[11];
    float* out = (float*)d_out;

    cudaFuncSetAttribute(pair_kernel,
                         cudaFuncAttributeMaxDynamicSharedMemorySize, SMEM_BYTES);

    prep_kernel<<<(N_ATOMS + 255) / 256, 256>>>(Z, ac, ae, pc, pe, ke, d2A, e2m, out);
    pair_kernel<<<NBLK, NTHR, SMEM_BYTES>>>(dist, cutv, ii, jj, out);
}